// round 13
// baseline (speedup 1.0000x reference)
#include <cuda_runtime.h>
#include <math.h>

#define B      8
#define DIM    64
#define HEADS  2
#define CH     32
#define HH     256
#define WW     256
#define NPIX   65536
#define QKVC   192

typedef unsigned long long u64;
__device__ __forceinline__ void fma2(u64& d, u64 a, u64 b, u64 c) {
    asm("fma.rn.f32x2 %0,%1,%2,%3;" : "=l"(d) : "l"(a), "l"(b), "l"(c));
}
__device__ __forceinline__ u64 pk2(float lo, float hi) {
    u64 r; asm("mov.b64 %0,{%1,%2};" : "=l"(r) : "f"(lo), "f"(hi)); return r;
}
__device__ __forceinline__ float2 upk2(u64 v) {
    float2 r; asm("mov.b64 {%0,%1},%2;" : "=f"(r.x), "=f"(r.y) : "l"(v)); return r;
}

__device__ float g_mid[(size_t)B * QKVC * NPIX];
__device__ float g_v[(size_t)B * DIM * NPIX];     // v after depthwise
__device__ float g_gram[B * HEADS * CH * CH];
__device__ float g_sqn[B * 2 * DIM];
__device__ float g_A[B * HEADS * CH * CH];
__device__ float g_M[B * DIM * DIM];

__global__ void k_zero() {
    int t = blockIdx.x * blockDim.x + threadIdx.x;
    if (t < B * HEADS * CH * CH) g_gram[t] = 0.f;
    if (t < B * 2 * DIM)         g_sqn[t]  = 0.f;
}

// ---- kernel 1: 1x1 conv (unchanged winner from R10) ------------------------
__global__ __launch_bounds__(256) void k_conv1(const float* __restrict__ x,
                                               const float* __restrict__ wqkv) {
    extern __shared__ float sm[];
    float* ws = sm;             // [64][96]
    float* xs = sm + 64 * 96;   // [64][128]

    const int b  = blockIdx.y;
    const int z  = blockIdx.z;
    const long n0 = (long)blockIdx.x * 128;
    const int tx = threadIdx.x, ty = threadIdx.y;
    const int tid = ty * 16 + tx;

    const float* wsrc = wqkv + z * 96 * 64;
    for (int idx = tid; idx < 96 * 64; idx += 256) {
        int oc = idx >> 6, k = idx & 63;
        ws[k * 96 + oc] = wsrc[idx];
    }
    const float* xb = x + (size_t)b * DIM * NPIX + n0;
    for (int idx = tid; idx < 64 * 32; idx += 256) {
        int ic = idx >> 5, pv = idx & 31;
        ((float4*)&xs[ic * 128])[pv] = ((const float4*)(xb + (size_t)ic * NPIX))[pv];
    }
    __syncthreads();

    u64 acc[6][4];
#pragma unroll
    for (int p = 0; p < 6; p++)
#pragma unroll
        for (int j = 0; j < 4; j++) acc[p][j] = 0ull;

    const int ocb = ty * 6;
#pragma unroll 4
    for (int k = 0; k < 64; k++) {
        const float* wrow = ws + k * 96 + ocb;
        u64 wd[6];
#pragma unroll
        for (int p = 0; p < 6; p++) {
            float w = wrow[p];
            wd[p] = pk2(w, w);
        }
        u64 xp[4];
#pragma unroll
        for (int j = 0; j < 4; j++)
            xp[j] = *(const u64*)&xs[k * 128 + 2 * (tx + 16 * j)];
#pragma unroll
        for (int p = 0; p < 6; p++)
#pragma unroll
            for (int j = 0; j < 4; j++)
                fma2(acc[p][j], wd[p], xp[j], acc[p][j]);
    }

    float* ob = g_mid + (size_t)b * QKVC * NPIX + (size_t)(z * 96) * NPIX + n0;
#pragma unroll
    for (int p = 0; p < 6; p++)
#pragma unroll
        for (int j = 0; j < 4; j++) {
            float2 r = upk2(acc[p][j]);
            *(float2*)&ob[(size_t)(ocb + p) * NPIX + 2 * (tx + 16 * j)] = r;
        }
}

// ---- kernel 2: fused dw(q,k) + sqn + Gram. Block = one row of one (b,h) ----
// 256 thr: dw phase thread=(ch=tid>>2, strip=tid&3): 64-px strip of channel ch,
// sliding float4 window over gmem rows y-1..y+1. Then gram on smem tile.
__global__ __launch_bounds__(256) void k_dwgram(const float* __restrict__ wdw) {
    extern __shared__ float qk_s[];   // [64][260]  (65 KB -> 3 CTA/SM)

    const int bh = blockIdx.y;
    const int b = bh >> 1, h = bh & 1;
    const int y = blockIdx.x;
    const int tid = threadIdx.x;

    // ---- dw phase ----
    {
        const int ch = tid >> 2;          // 0..31 q, 32..63 k
        const int strip = tid & 3;
        const int s0 = strip * 64;
        const int gc = (ch < 32) ? h * CH + ch : DIM + h * CH + (ch - 32);
        const float* plane = g_mid + ((size_t)b * QKVC + gc) * NPIX;

        float w[9];
#pragma unroll
        for (int t = 0; t < 9; t++) w[t] = wdw[gc * 9 + t];

        const bool v0 = (y > 0), v2 = (y < HH - 1);
        const float* rp0 = plane + (size_t)(y - 1) * WW;
        const float* rp1 = plane + (size_t)y * WW;
        const float* rp2 = plane + (size_t)(y + 1) * WW;

        float lft[3];
        float4 cur[3];
        const float4 z4 = make_float4(0.f, 0.f, 0.f, 0.f);
        lft[0] = (v0 && s0 > 0) ? rp0[s0 - 1] : 0.f;
        lft[1] = (s0 > 0)       ? rp1[s0 - 1] : 0.f;
        lft[2] = (v2 && s0 > 0) ? rp2[s0 - 1] : 0.f;
        cur[0] = v0 ? *(const float4*)(rp0 + s0) : z4;
        cur[1] =      *(const float4*)(rp1 + s0);
        cur[2] = v2 ? *(const float4*)(rp2 + s0) : z4;

        float sq = 0.f;
#pragma unroll 4
        for (int j = 0; j < 16; j++) {
            float4 nxt[3];
            if (j < 15) {
                const int c4 = s0 + 4 * j + 4;
                nxt[0] = v0 ? *(const float4*)(rp0 + c4) : z4;
                nxt[1] =      *(const float4*)(rp1 + c4);
                nxt[2] = v2 ? *(const float4*)(rp2 + c4) : z4;
            } else {
                const int ce = s0 + 64;
                const bool okc = (ce < WW);
                nxt[0] = make_float4((v0 && okc) ? rp0[ce] : 0.f, 0.f, 0.f, 0.f);
                nxt[1] = make_float4(okc ? rp1[ce] : 0.f, 0.f, 0.f, 0.f);
                nxt[2] = make_float4((v2 && okc) ? rp2[ce] : 0.f, 0.f, 0.f, 0.f);
            }
            float o0 = 0.f, o1 = 0.f, o2 = 0.f, o3 = 0.f;
#pragma unroll
            for (int r = 0; r < 3; r++) {
                float w0 = w[3 * r], w1 = w[3 * r + 1], w2 = w[3 * r + 2];
                o0 = fmaf(w0, lft[r],   fmaf(w1, cur[r].x, fmaf(w2, cur[r].y, o0)));
                o1 = fmaf(w0, cur[r].x, fmaf(w1, cur[r].y, fmaf(w2, cur[r].z, o1)));
                o2 = fmaf(w0, cur[r].y, fmaf(w1, cur[r].z, fmaf(w2, cur[r].w, o2)));
                o3 = fmaf(w0, cur[r].z, fmaf(w1, cur[r].w, fmaf(w2, nxt[r].x, o3)));
            }
            *(float4*)&qk_s[ch * 260 + s0 + 4 * j] = make_float4(o0, o1, o2, o3);
            sq = fmaf(o0, o0, fmaf(o1, o1, fmaf(o2, o2, fmaf(o3, o3, sq))));
#pragma unroll
            for (int r = 0; r < 3; r++) { lft[r] = cur[r].w; cur[r] = nxt[r]; }
        }
        // reduce sq across the 4 strips (adjacent lanes) and accumulate
        sq += __shfl_xor_sync(0xffffffffu, sq, 1);
        sq += __shfl_xor_sync(0xffffffffu, sq, 2);
        if (strip == 0) {
            int si = (ch < 32) ? b * 2 * DIM + h * CH + ch
                               : b * 2 * DIM + DIM + h * CH + (ch - 32);
            atomicAdd(&g_sqn[si], sq);
        }
    }
    __syncthreads();

    // ---- gram phase: 4 groups x (8x8); thread (gi,gj) owns {gi+8a}x{gj+8b} --
    const int g  = tid >> 6;
    const int gi = (tid >> 3) & 7;
    const int gj = tid & 7;

    u64 acc[4][4];
#pragma unroll
    for (int a = 0; a < 4; a++)
#pragma unroll
        for (int bb = 0; bb < 4; bb++) acc[a][bb] = 0ull;

#pragma unroll 4
    for (int p = g * 64; p < g * 64 + 64; p += 4) {
        ulonglong2 qa[4], kb[4];
#pragma unroll
        for (int a = 0; a < 4; a++) qa[a] = *(ulonglong2*)&qk_s[(gi + 8 * a) * 260 + p];
#pragma unroll
        for (int bb = 0; bb < 4; bb++) kb[bb] = *(ulonglong2*)&qk_s[(32 + gj + 8 * bb) * 260 + p];
#pragma unroll
        for (int a = 0; a < 4; a++)
#pragma unroll
            for (int bb = 0; bb < 4; bb++) {
                fma2(acc[a][bb], qa[a].x, kb[bb].x, acc[a][bb]);
                fma2(acc[a][bb], qa[a].y, kb[bb].y, acc[a][bb]);
            }
    }

    __syncthreads();
    float* red = qk_s;   // reuse: needs 4096 floats
#pragma unroll
    for (int a = 0; a < 4; a++)
#pragma unroll
        for (int bb = 0; bb < 4; bb++) {
            float2 r = upk2(acc[a][bb]);
            red[g * 1024 + (gi + 8 * a) * 32 + gj + 8 * bb] = r.x + r.y;
        }
    __syncthreads();
    for (int t = tid; t < 1024; t += 256) {
        float s = red[t] + red[1024 + t] + red[2048 + t] + red[3072 + t];
        atomicAdd(&g_gram[bh * 1024 + t], s);
    }
}

// ---- kernel 3: depthwise 3x3 for v channels. 64x32 tile, 8 px/thread -------
__global__ void k_dwv(const float* __restrict__ wdw) {
    const int bz = blockIdx.z;
    const int cl = bz & 63;
    const int b  = bz >> 6;
    const int c  = 128 + cl;
    const int x0 = blockIdx.x * 64, y0 = blockIdx.y * 32;

    __shared__ float tile[34][68];
    const float* in = g_mid + ((size_t)b * QKVC + c) * NPIX;
    const int tx = threadIdx.x, ty = threadIdx.y;
    const int tid = ty * 8 + tx;

    for (int idx = tid; idx < 34 * 66; idx += 256) {
        int yy = idx / 66, xx = idx - yy * 66;
        int gy = y0 + yy - 1, gx = x0 + xx - 1;
        tile[yy][xx] = (gy >= 0 && gy < HH && gx >= 0 && gx < WW)
                           ? in[gy * WW + gx] : 0.f;
    }
    __syncthreads();

    float w[9];
#pragma unroll
    for (int t = 0; t < 9; t++) w[t] = wdw[c * 9 + t];

#pragma unroll
    for (int half = 0; half < 2; half++) {
        const int bcol = 32 * half + 4 * tx;
        float o0 = 0.f, o1 = 0.f, o2 = 0.f, o3 = 0.f;
#pragma unroll
        for (int ky = 0; ky < 3; ky++) {
            float4 lo = *(float4*)&tile[ty + ky][bcol];
            float4 hi = *(float4*)&tile[ty + ky][bcol + 4];
            float w0 = w[ky * 3], w1 = w[ky * 3 + 1], w2 = w[ky * 3 + 2];
            o0 = fmaf(w0, lo.x, fmaf(w1, lo.y, fmaf(w2, lo.z, o0)));
            o1 = fmaf(w0, lo.y, fmaf(w1, lo.z, fmaf(w2, lo.w, o1)));
            o2 = fmaf(w0, lo.z, fmaf(w1, lo.w, fmaf(w2, hi.x, o2)));
            o3 = fmaf(w0, lo.w, fmaf(w1, hi.x, fmaf(w2, hi.y, o3)));
        }
        *(float4*)&g_v[((size_t)b * DIM + cl) * NPIX + (size_t)(y0 + ty) * WW + x0 + bcol] =
            make_float4(o0, o1, o2, o3);
    }
}

// ---- kernel 4: normalize + triple top-k softmax + combine ------------------
__global__ void k_comb(const float* __restrict__ temp, const float* __restrict__ a1,
                       const float* __restrict__ a2, const float* __restrict__ a3) {
    const int bh = blockIdx.x;
    const int b = bh >> 1, h = bh & 1;
    const int i = threadIdx.x;

    __shared__ float nks[CH];
    float nq = fmaxf(sqrtf(g_sqn[b * 2 * DIM + h * CH + i]), 1e-12f);
    float nk = fmaxf(sqrtf(g_sqn[b * 2 * DIM + DIM + h * CH + i]), 1e-12f);
    nks[i] = nk;
    __syncthreads();

    const float t = temp[h];
    float v[CH];
#pragma unroll
    for (int j = 0; j < CH; j++)
        v[j] = g_gram[bh * CH * CH + i * CH + j] / nq * t / nks[j];

    int rank[CH];
#pragma unroll
    for (int j = 0; j < CH; j++) {
        int r = 0; float vj = v[j];
#pragma unroll
        for (int l = 0; l < CH; l++)
            r += (v[l] > vj) || (v[l] == vj && l < j);
        rank[j] = r;
    }
    float mx = -1e30f;
#pragma unroll
    for (int j = 0; j < CH; j++) mx = fmaxf(mx, v[j]);
    float e[CH], s16 = 0.f, s21 = 0.f, s24 = 0.f;
#pragma unroll
    for (int j = 0; j < CH; j++) {
        float ev = expf(v[j] - mx);
        e[j] = ev;
        if (rank[j] < 16) s16 += ev;
        if (rank[j] < 21) s21 += ev;
        if (rank[j] < 24) s24 += ev;
    }
    const float w1 = a1[0] / s16, w2 = a2[0] / s21, w3 = a3[0] / s24;
#pragma unroll
    for (int j = 0; j < CH; j++) {
        float coef = (rank[j] < 16 ? w1 : 0.f) + (rank[j] < 21 ? w2 : 0.f)
                   + (rank[j] < 24 ? w3 : 0.f);
        g_A[bh * CH * CH + i * CH + j] = e[j] * coef;
    }
}

// ---- kernel 5: M[b] = W_proj @ blockdiag(A) --------------------------------
__global__ void k_buildM(const float* __restrict__ wproj) {
    const int b = blockIdx.x;
    __shared__ float As[HEADS * CH * CH];
    __shared__ float Ws[DIM * DIM];
    const int tid = threadIdx.x;
    for (int idx = tid; idx < HEADS * CH * CH; idx += 128) As[idx] = g_A[b * HEADS * CH * CH + idx];
    for (int idx = tid; idx < DIM * DIM; idx += 128)       Ws[idx] = wproj[idx];
    __syncthreads();
#pragma unroll
    for (int m = 0; m < 32; m++) {
        int idx = tid + 128 * m;
        int o = idx >> 6, ci = idx & 63;
        int h = ci >> 5, cj = ci & 31;
        float s = 0.f;
#pragma unroll
        for (int cp = 0; cp < CH; cp++)
            s = fmaf(Ws[o * DIM + h * CH + cp], As[h * CH * CH + cp * CH + cj], s);
        g_M[b * DIM * DIM + idx] = s;
    }
}

// ---- kernel 6: out = M[b] @ v. Dup'd u64 M in smem; 4 oc x 8 px-pairs ------
__global__ __launch_bounds__(256) void k_out(float* __restrict__ out) {
    extern __shared__ float sm[];
    u64*   ms2 = (u64*)sm;            // [64ci][64oc] u64 {m,m}
    float* vs  = sm + 64 * 64 * 2;    // [64][256]
    const int b = blockIdx.y;
    const long n0 = (long)blockIdx.x * 256;
    const int tx = threadIdx.x, ty = threadIdx.y;
    const int tid = ty * 16 + tx;

    const float* Mb = g_M + b * DIM * DIM;
    for (int idx = tid; idx < DIM * DIM; idx += 256) {
        int o = idx >> 6, ci = idx & 63;
        float m = Mb[idx];
        ms2[ci * DIM + o] = pk2(m, m);
    }
    const float* vg = g_v + (size_t)b * DIM * NPIX + n0;
    for (int idx = tid; idx < 64 * 64; idx += 256) {
        int ci = idx >> 6, pv = idx & 63;
        ((float4*)&vs[ci * 256])[pv] = ((const float4*)(vg + (size_t)ci * NPIX))[pv];
    }
    __syncthreads();

    u64 acc[4][8];
#pragma unroll
    for (int i = 0; i < 4; i++)
#pragma unroll
        for (int j = 0; j < 8; j++) acc[i][j] = 0ull;

    const int ob4 = ty * 4;
#pragma unroll 4
    for (int ci = 0; ci < 64; ci++) {
        const ulonglong2* wp = (const ulonglong2*)(ms2 + ci * DIM + ob4);
        ulonglong2 w01 = wp[0], w23 = wp[1];
        u64 wd[4] = {w01.x, w01.y, w23.x, w23.y};
        u64 xp[8];
#pragma unroll
        for (int j = 0; j < 8; j++)
            xp[j] = *(const u64*)&vs[ci * 256 + 2 * (tx + 16 * j)];
#pragma unroll
        for (int i = 0; i < 4; i++)
#pragma unroll
            for (int j = 0; j < 8; j++)
                fma2(acc[i][j], wd[i], xp[j], acc[i][j]);
    }

    float* ob = out + (size_t)b * DIM * NPIX + n0;
#pragma unroll
    for (int i = 0; i < 4; i++)
#pragma unroll
        for (int j = 0; j < 8; j++) {
            float2 r = upk2(acc[i][j]);
            *(float2*)&ob[(size_t)(ob4 + i) * NPIX + 2 * (tx + 16 * j)] = r;
        }
}

extern "C" void kernel_launch(void* const* d_in, const int* in_sizes, int n_in,
                              void* d_out, int out_size) {
    const float* x     = (const float*)d_in[0];
    const float* wqkv  = (const float*)d_in[1];
    const float* wdw   = (const float*)d_in[2];
    const float* wproj = (const float*)d_in[3];
    const float* temp  = (const float*)d_in[4];
    const float* a1    = (const float*)d_in[5];
    const float* a2    = (const float*)d_in[6];
    const float* a3    = (const float*)d_in[7];
    float* out = (float*)d_out;

    cudaFuncSetAttribute(k_conv1,  cudaFuncAttributeMaxDynamicSharedMemorySize, 65536);
    cudaFuncSetAttribute(k_dwgram, cudaFuncAttributeMaxDynamicSharedMemorySize, 66560);
    cudaFuncSetAttribute(k_out,    cudaFuncAttributeMaxDynamicSharedMemorySize, 98304);

    k_zero<<<64, 256>>>();
    k_conv1<<<dim3(512, 8, 2), dim3(16, 16), 57344>>>(x, wqkv);
    k_dwgram<<<dim3(256, 16), 256, 66560>>>(wdw);
    k_dwv<<<dim3(4, 8, B * 64), dim3(8, 32)>>>(wdw);
    k_comb<<<16, 32>>>(temp, a1, a2, a3);
    k_buildM<<<8, 128>>>(wproj);
    k_out<<<dim3(256, 8), dim3(16, 16), 98304>>>(out);
}

// round 15
// speedup vs baseline: 1.2281x; 1.2281x over previous
#include <cuda_runtime.h>
#include <math.h>

#define B      8
#define DIM    64
#define HEADS  2
#define CH     32
#define HH     256
#define WW     256
#define NPIX   65536
#define QKVC   192

typedef unsigned long long u64;
__device__ __forceinline__ void fma2(u64& d, u64 a, u64 b, u64 c) {
    asm("fma.rn.f32x2 %0,%1,%2,%3;" : "=l"(d) : "l"(a), "l"(b), "l"(c));
}
__device__ __forceinline__ u64 pk2(float lo, float hi) {
    u64 r; asm("mov.b64 %0,{%1,%2};" : "=l"(r) : "f"(lo), "f"(hi)); return r;
}
__device__ __forceinline__ float2 upk2(u64 v) {
    float2 r; asm("mov.b64 {%0,%1},%2;" : "=f"(r.x), "=f"(r.y) : "l"(v)); return r;
}

__device__ float g_mid[(size_t)B * QKVC * NPIX];
__device__ float g_qkv[(size_t)B * QKVC * NPIX];
__device__ float g_gram[B * HEADS * CH * CH];
__device__ float g_sqn[B * 2 * DIM];
__device__ float g_A[B * HEADS * CH * CH];
__device__ float g_M[B * DIM * DIM];

__global__ void k_zero() {
    int t = blockIdx.x * blockDim.x + threadIdx.x;
    if (t < B * HEADS * CH * CH) g_gram[t] = 0.f;
    if (t < B * 2 * DIM)         g_sqn[t]  = 0.f;
}

// ---- kernel 1: 1x1 conv (unchanged R11 winner) -----------------------------
__global__ __launch_bounds__(256) void k_conv1(const float* __restrict__ x,
                                               const float* __restrict__ wqkv) {
    extern __shared__ float sm[];
    float* ws = sm;             // [64][96]
    float* xs = sm + 64 * 96;   // [64][128]

    const int b  = blockIdx.y;
    const int z  = blockIdx.z;
    const long n0 = (long)blockIdx.x * 128;
    const int tx = threadIdx.x, ty = threadIdx.y;
    const int tid = ty * 16 + tx;

    const float* wsrc = wqkv + z * 96 * 64;
    for (int idx = tid; idx < 96 * 64; idx += 256) {
        int oc = idx >> 6, k = idx & 63;
        ws[k * 96 + oc] = wsrc[idx];
    }
    const float* xb = x + (size_t)b * DIM * NPIX + n0;
    for (int idx = tid; idx < 64 * 32; idx += 256) {
        int ic = idx >> 5, pv = idx & 31;
        ((float4*)&xs[ic * 128])[pv] = ((const float4*)(xb + (size_t)ic * NPIX))[pv];
    }
    __syncthreads();

    u64 acc[6][4];
#pragma unroll
    for (int p = 0; p < 6; p++)
#pragma unroll
        for (int j = 0; j < 4; j++) acc[p][j] = 0ull;

    const int ocb = ty * 6;
#pragma unroll 4
    for (int k = 0; k < 64; k++) {
        const float* wrow = ws + k * 96 + ocb;
        u64 wd[6];
#pragma unroll
        for (int p = 0; p < 6; p++) {
            float w = wrow[p];
            wd[p] = pk2(w, w);
        }
        u64 xp[4];
#pragma unroll
        for (int j = 0; j < 4; j++)
            xp[j] = *(const u64*)&xs[k * 128 + 2 * (tx + 16 * j)];
#pragma unroll
        for (int p = 0; p < 6; p++)
#pragma unroll
            for (int j = 0; j < 4; j++)
                fma2(acc[p][j], wd[p], xp[j], acc[p][j]);
    }

    float* ob = g_mid + (size_t)b * QKVC * NPIX + (size_t)(z * 96) * NPIX + n0;
#pragma unroll
    for (int p = 0; p < 6; p++)
#pragma unroll
        for (int j = 0; j < 4; j++) {
            float2 r = upk2(acc[p][j]);
            *(float2*)&ob[(size_t)(ocb + p) * NPIX + 2 * (tx + 16 * j)] = r;
        }
}

// ---- kernel 2: depthwise 3x3 + fused sqn. 2 channels/block, 64x32 tile -----
__global__ void k_dw(const float* __restrict__ wdw) {
    const int bz = blockIdx.z;           // b*96 + cz
    const int cz = bz % 96;
    const int b  = bz / 96;
    const int c0 = 2 * cz;               // channel pair (c0, c0+1)
    const int x0 = blockIdx.x * 64, y0 = blockIdx.y * 32;

    __shared__ float tile[2][34][68];
    const float* in0 = g_mid + ((size_t)b * QKVC + c0) * NPIX;
    const float* in1 = in0 + NPIX;
    const int tx = threadIdx.x, ty = threadIdx.y;
    const int tid = ty * 8 + tx;

    for (int idx = tid; idx < 34 * 66; idx += 256) {
        int yy = idx / 66, xx = idx - yy * 66;
        int gy = y0 + yy - 1, gx = x0 + xx - 1;
        bool ok = (gy >= 0 && gy < HH && gx >= 0 && gx < WW);
        int off = gy * WW + gx;
        tile[0][yy][xx] = ok ? in0[off] : 0.f;
        tile[1][yy][xx] = ok ? in1[off] : 0.f;
    }
    __syncthreads();

    float sqa[2] = {0.f, 0.f};
#pragma unroll
    for (int cc = 0; cc < 2; cc++) {
        const int c = c0 + cc;
        float w[9];
#pragma unroll
        for (int t = 0; t < 9; t++) w[t] = wdw[c * 9 + t];

#pragma unroll
        for (int half = 0; half < 2; half++) {
            const int bcol = 32 * half + 4 * tx;
            float o0 = 0.f, o1 = 0.f, o2 = 0.f, o3 = 0.f;
#pragma unroll
            for (int ky = 0; ky < 3; ky++) {
                float4 lo = *(float4*)&tile[cc][ty + ky][bcol];
                float4 hi = *(float4*)&tile[cc][ty + ky][bcol + 4];
                float w0 = w[ky * 3], w1 = w[ky * 3 + 1], w2 = w[ky * 3 + 2];
                o0 = fmaf(w0, lo.x, fmaf(w1, lo.y, fmaf(w2, lo.z, o0)));
                o1 = fmaf(w0, lo.y, fmaf(w1, lo.z, fmaf(w2, lo.w, o1)));
                o2 = fmaf(w0, lo.z, fmaf(w1, lo.w, fmaf(w2, hi.x, o2)));
                o3 = fmaf(w0, lo.w, fmaf(w1, hi.x, fmaf(w2, hi.y, o3)));
            }
            *(float4*)&g_qkv[((size_t)b * QKVC + c) * NPIX
                             + (size_t)(y0 + ty) * WW + x0 + bcol] =
                make_float4(o0, o1, o2, o3);
            sqa[cc] = fmaf(o0, o0, fmaf(o1, o1, fmaf(o2, o2, fmaf(o3, o3, sqa[cc]))));
        }
    }

    if (c0 < 2 * DIM) {
        float s0 = sqa[0], s1 = sqa[1];
#pragma unroll
        for (int o = 16; o; o >>= 1) {
            s0 += __shfl_down_sync(0xffffffffu, s0, o);
            s1 += __shfl_down_sync(0xffffffffu, s1, o);
        }
        __shared__ float red[8][2];
        if ((tid & 31) == 0) { red[tid >> 5][0] = s0; red[tid >> 5][1] = s1; }
        __syncthreads();
        if (tid == 0) {
            float t0 = 0.f, t1 = 0.f;
#pragma unroll
            for (int wv = 0; wv < 8; wv++) { t0 += red[wv][0]; t1 += red[wv][1]; }
            atomicAdd(&g_sqn[b * 2 * DIM + c0],     t0);
            atomicAdd(&g_sqn[b * 2 * DIM + c0 + 1], t1);
        }
    }
}

// ---- kernel 3: Gram G = q@k^T (unchanged R11 winner) -----------------------
__global__ __launch_bounds__(256) void k_gram() {
    __shared__ float qs[32][132];
    __shared__ float ks[32][132];

    const int bh = blockIdx.y;
    const int b = bh >> 1, h = bh & 1;
    const long n0 = (long)blockIdx.x * 1024;
    const float* qg = g_qkv + ((size_t)b * QKVC + h * CH) * NPIX + n0;
    const float* kg = g_qkv + ((size_t)b * QKVC + DIM + h * CH) * NPIX + n0;
    const int tid = threadIdx.x;
    const int g  = tid >> 6;
    const int gi = (tid >> 3) & 7;
    const int gj = tid & 7;

    u64 acc[4][4];
#pragma unroll
    for (int a = 0; a < 4; a++)
#pragma unroll
        for (int bb = 0; bb < 4; bb++) acc[a][bb] = 0ull;

    for (int s = 0; s < 8; s++) {
        __syncthreads();
        for (int idx = tid; idx < 1024; idx += 256) {
            int r = idx >> 5, pv = idx & 31;
            ((float4*)qs[r])[pv] = ((const float4*)(qg + (size_t)r * NPIX + s * 128))[pv];
            ((float4*)ks[r])[pv] = ((const float4*)(kg + (size_t)r * NPIX + s * 128))[pv];
        }
        __syncthreads();
#pragma unroll 4
        for (int p = g * 32; p < g * 32 + 32; p += 4) {
            ulonglong2 qa[4], kb[4];
#pragma unroll
            for (int a = 0; a < 4; a++) qa[a] = *(ulonglong2*)&qs[gi + 8 * a][p];
#pragma unroll
            for (int bb = 0; bb < 4; bb++) kb[bb] = *(ulonglong2*)&ks[gj + 8 * bb][p];
#pragma unroll
            for (int a = 0; a < 4; a++)
#pragma unroll
                for (int bb = 0; bb < 4; bb++) {
                    fma2(acc[a][bb], qa[a].x, kb[bb].x, acc[a][bb]);
                    fma2(acc[a][bb], qa[a].y, kb[bb].y, acc[a][bb]);
                }
        }
    }

    __syncthreads();
    float* red = &qs[0][0];
#pragma unroll
    for (int a = 0; a < 4; a++)
#pragma unroll
        for (int bb = 0; bb < 4; bb++) {
            float2 r = upk2(acc[a][bb]);
            red[g * 1024 + (gi + 8 * a) * 32 + gj + 8 * bb] = r.x + r.y;
        }
    __syncthreads();
    for (int t = tid; t < 1024; t += 256) {
        float s = red[t] + red[1024 + t] + red[2048 + t] + red[3072 + t];
        atomicAdd(&g_gram[bh * 1024 + t], s);
    }
}

// ---- kernel 4: normalize + triple top-k softmax + combine ------------------
__global__ void k_comb(const float* __restrict__ temp, const float* __restrict__ a1,
                       const float* __restrict__ a2, const float* __restrict__ a3) {
    const int bh = blockIdx.x;
    const int b = bh >> 1, h = bh & 1;
    const int i = threadIdx.x;

    __shared__ float nks[CH];
    float nq = fmaxf(sqrtf(g_sqn[b * 2 * DIM + h * CH + i]), 1e-12f);
    float nk = fmaxf(sqrtf(g_sqn[b * 2 * DIM + DIM + h * CH + i]), 1e-12f);
    nks[i] = nk;
    __syncthreads();

    const float t = temp[h];
    float v[CH];
#pragma unroll
    for (int j = 0; j < CH; j++)
        v[j] = g_gram[bh * CH * CH + i * CH + j] / nq * t / nks[j];

    int rank[CH];
#pragma unroll
    for (int j = 0; j < CH; j++) {
        int r = 0; float vj = v[j];
#pragma unroll
        for (int l = 0; l < CH; l++)
            r += (v[l] > vj) || (v[l] == vj && l < j);
        rank[j] = r;
    }
    float mx = -1e30f;
#pragma unroll
    for (int j = 0; j < CH; j++) mx = fmaxf(mx, v[j]);
    float e[CH], s16 = 0.f, s21 = 0.f, s24 = 0.f;
#pragma unroll
    for (int j = 0; j < CH; j++) {
        float ev = expf(v[j] - mx);
        e[j] = ev;
        if (rank[j] < 16) s16 += ev;
        if (rank[j] < 21) s21 += ev;
        if (rank[j] < 24) s24 += ev;
    }
    const float w1 = a1[0] / s16, w2 = a2[0] / s21, w3 = a3[0] / s24;
#pragma unroll
    for (int j = 0; j < CH; j++) {
        float coef = (rank[j] < 16 ? w1 : 0.f) + (rank[j] < 21 ? w2 : 0.f)
                   + (rank[j] < 24 ? w3 : 0.f);
        g_A[bh * CH * CH + i * CH + j] = e[j] * coef;
    }
}

// ---- kernel 5: M[b] = W_proj @ blockdiag(A) --------------------------------
__global__ void k_buildM(const float* __restrict__ wproj) {
    const int b = blockIdx.x;
    __shared__ float As[HEADS * CH * CH];
    __shared__ float Ws[DIM * DIM];
    const int tid = threadIdx.x;
    for (int idx = tid; idx < HEADS * CH * CH; idx += 128) As[idx] = g_A[b * HEADS * CH * CH + idx];
    for (int idx = tid; idx < DIM * DIM; idx += 128)       Ws[idx] = wproj[idx];
    __syncthreads();
#pragma unroll
    for (int m = 0; m < 32; m++) {
        int idx = tid + 128 * m;
        int o = idx >> 6, ci = idx & 63;
        int h = ci >> 5, cj = ci & 31;
        float s = 0.f;
#pragma unroll
        for (int cp = 0; cp < CH; cp++)
            s = fmaf(Ws[o * DIM + h * CH + cp], As[h * CH * CH + cp * CH + cj], s);
        g_M[b * DIM * DIM + idx] = s;
    }
}

// ---- kernel 6: out = M[b] @ v. 8 oc x 4 px-pairs; FLAT 256-thread block ----
__global__ __launch_bounds__(256) void k_out(float* __restrict__ out) {
    extern __shared__ float sm[];
    u64*   ms2 = (u64*)sm;            // [64ci][64oc] u64 {m,m}
    float* vs  = sm + 64 * 64 * 2;    // [64][256]
    const int b = blockIdx.y;
    const long n0 = (long)blockIdx.x * 256;
    const int tid = threadIdx.x;      // 0..255 (flat launch!)
    const int og = tid >> 5;          // 0..7  -> oc group (warp-uniform)
    const int pg = tid & 31;          // 0..31 -> pixel-pair lane

    const float* Mb = g_M + b * DIM * DIM;
    for (int idx = tid; idx < DIM * DIM; idx += 256) {
        int o = idx >> 6, ci = idx & 63;
        float m = Mb[idx];
        ms2[ci * DIM + o] = pk2(m, m);
    }
    const float* vg = g_qkv + ((size_t)b * QKVC + 2 * DIM) * NPIX + n0;
    for (int idx = tid; idx < 64 * 64; idx += 256) {
        int ci = idx >> 6, pv = idx & 63;
        ((float4*)&vs[ci * 256])[pv] = ((const float4*)(vg + (size_t)ci * NPIX))[pv];
    }
    __syncthreads();

    u64 acc[8][4];
#pragma unroll
    for (int i = 0; i < 8; i++)
#pragma unroll
        for (int j = 0; j < 4; j++) acc[i][j] = 0ull;

    const int ob8 = og * 8;
#pragma unroll 4
    for (int ci = 0; ci < 64; ci++) {
        const ulonglong2* wp = (const ulonglong2*)(ms2 + ci * DIM + ob8);
        ulonglong2 wA = wp[0], wB = wp[1], wC = wp[2], wD = wp[3];
        u64 wd[8] = {wA.x, wA.y, wB.x, wB.y, wC.x, wC.y, wD.x, wD.y};
        u64 xp[4];
#pragma unroll
        for (int j = 0; j < 4; j++)
            xp[j] = *(const u64*)&vs[ci * 256 + 2 * (pg + 32 * j)];
#pragma unroll
        for (int i = 0; i < 8; i++)
#pragma unroll
            for (int j = 0; j < 4; j++)
                fma2(acc[i][j], wd[i], xp[j], acc[i][j]);
    }

    float* ob = out + (size_t)b * DIM * NPIX + n0;
#pragma unroll
    for (int i = 0; i < 8; i++)
#pragma unroll
        for (int j = 0; j < 4; j++) {
            float2 r = upk2(acc[i][j]);
            *(float2*)&ob[(size_t)(ob8 + i) * NPIX + 2 * (pg + 32 * j)] = r;
        }
}

extern "C" void kernel_launch(void* const* d_in, const int* in_sizes, int n_in,
                              void* d_out, int out_size) {
    const float* x     = (const float*)d_in[0];
    const float* wqkv  = (const float*)d_in[1];
    const float* wdw   = (const float*)d_in[2];
    const float* wproj = (const float*)d_in[3];
    const float* temp  = (const float*)d_in[4];
    const float* a1    = (const float*)d_in[5];
    const float* a2    = (const float*)d_in[6];
    const float* a3    = (const float*)d_in[7];
    float* out = (float*)d_out;

    cudaFuncSetAttribute(k_conv1, cudaFuncAttributeMaxDynamicSharedMemorySize, 65536);
    cudaFuncSetAttribute(k_out,   cudaFuncAttributeMaxDynamicSharedMemorySize, 98304);

    k_zero<<<64, 256>>>();
    k_conv1<<<dim3(512, 8, 2), dim3(16, 16), 57344>>>(x, wqkv);
    k_dw<<<dim3(4, 8, B * 96), dim3(8, 32)>>>(wdw);
    k_gram<<<dim3(64, 16), 256>>>();
    k_comb<<<16, 32>>>(temp, a1, a2, a3);
    k_buildM<<<8, 128>>>(wproj);
    k_out<<<dim3(256, 8), dim3(256, 1), 98304>>>(out);
}

// round 17
// speedup vs baseline: 1.3787x; 1.1226x over previous
#include <cuda_runtime.h>
#include <math.h>
#include <stdint.h>

#define B      8
#define DIM    64
#define HEADS  2
#define CH     32
#define HH     256
#define WW     256
#define NPIX   65536
#define QKVC   192

typedef unsigned long long u64;
__device__ __forceinline__ void fma2(u64& d, u64 a, u64 b, u64 c) {
    asm("fma.rn.f32x2 %0,%1,%2,%3;" : "=l"(d) : "l"(a), "l"(b), "l"(c));
}
__device__ __forceinline__ u64 pk2(float lo, float hi) {
    u64 r; asm("mov.b64 %0,{%1,%2};" : "=l"(r) : "f"(lo), "f"(hi)); return r;
}
__device__ __forceinline__ float2 upk2(u64 v) {
    float2 r; asm("mov.b64 {%0,%1},%2;" : "=f"(r.x), "=f"(r.y) : "l"(v)); return r;
}
__device__ __forceinline__ uint32_t s2u32(const void* p) {
    uint32_t a;
    asm("{ .reg .u64 t; cvta.to.shared.u64 t, %1; cvt.u32.u64 %0, t; }" : "=r"(a) : "l"(p));
    return a;
}
__device__ __forceinline__ void cpa16(uint32_t s, const void* g) {
    asm volatile("cp.async.cg.shared.global [%0],[%1],16;" :: "r"(s), "l"(g));
}

__device__ float g_mid[(size_t)B * QKVC * NPIX];
__device__ float g_qkv[(size_t)B * QKVC * NPIX];
__device__ float g_gram[B * HEADS * CH * CH];
__device__ float g_sqn[B * 2 * DIM];
__device__ float g_A[B * HEADS * CH * CH];
__device__ float g_M[B * DIM * DIM];

__global__ void k_zero() {
    int t = blockIdx.x * blockDim.x + threadIdx.x;
    if (t < B * HEADS * CH * CH) g_gram[t] = 0.f;
    if (t < B * 2 * DIM)         g_sqn[t]  = 0.f;
}

// ---- kernel 1: 1x1 conv, even/odd-k lane split (no MOVs, no weight dup) ----
// grid (1024 px-tiles of 64, B, 2 oc-halves), block (16,16).
// Thread (tx,ty): oc 6ty..6ty+5, px {tx,tx+16,tx+32,tx+48}.
// acc lanes = even-k / odd-k partial sums; final = lo+hi.
__global__ __launch_bounds__(256) void k_conv1(const float* __restrict__ x,
                                               const float* __restrict__ wqkv) {
    __shared__ float ws[96 * 64];    // ws[oc][k]  (k-major, natural from wqkv)
    __shared__ float xs[64 * 66];    // xs[px][ic] (transposed, stride 66)

    const int b  = blockIdx.y;
    const int z  = blockIdx.z;
    const long n0 = (long)blockIdx.x * 64;
    const int tx = threadIdx.x, ty = threadIdx.y;
    const int tid = ty * 16 + tx;

    const float* wsrc = wqkv + z * 96 * 64;
    for (int idx = tid; idx < 96 * 64; idx += 256)
        ws[idx] = wsrc[idx];                    // [oc][ic] direct

    const float* xb = x + (size_t)b * DIM * NPIX + n0;
#pragma unroll
    for (int t = 0; t < 4; t++) {
        int idx = tid + t * 256;                // 1024 float4 total
        int ic = idx >> 4, p4 = idx & 15;
        float4 f = ((const float4*)(xb + (size_t)ic * NPIX))[p4];
        xs[(4 * p4 + 0) * 66 + ic] = f.x;
        xs[(4 * p4 + 1) * 66 + ic] = f.y;
        xs[(4 * p4 + 2) * 66 + ic] = f.z;
        xs[(4 * p4 + 3) * 66 + ic] = f.w;
    }
    __syncthreads();

    u64 acc[6][4];
#pragma unroll
    for (int p = 0; p < 6; p++)
#pragma unroll
        for (int j = 0; j < 4; j++) acc[p][j] = 0ull;

    const int oc0 = ty * 6;
#pragma unroll 4
    for (int kp = 0; kp < 32; kp++) {
        u64 wd[6], xp[4];
#pragma unroll
        for (int p = 0; p < 6; p++)
            wd[p] = *(const u64*)&ws[(oc0 + p) * 64 + 2 * kp];
#pragma unroll
        for (int j = 0; j < 4; j++)
            xp[j] = *(const u64*)&xs[(tx + 16 * j) * 66 + 2 * kp];
#pragma unroll
        for (int p = 0; p < 6; p++)
#pragma unroll
            for (int j = 0; j < 4; j++)
                fma2(acc[p][j], wd[p], xp[j], acc[p][j]);
    }

    float* ob = g_mid + (size_t)b * QKVC * NPIX + (size_t)(z * 96) * NPIX + n0;
#pragma unroll
    for (int p = 0; p < 6; p++)
#pragma unroll
        for (int j = 0; j < 4; j++) {
            float2 r = upk2(acc[p][j]);
            ob[(size_t)(oc0 + p) * NPIX + tx + 16 * j] = r.x + r.y;
        }
}

// ---- kernel 2: depthwise 3x3 + fused sqn. 2 channels/block (R15 winner) ----
__global__ void k_dw(const float* __restrict__ wdw) {
    const int bz = blockIdx.z;           // b*96 + cz
    const int cz = bz % 96;
    const int b  = bz / 96;
    const int c0 = 2 * cz;
    const int x0 = blockIdx.x * 64, y0 = blockIdx.y * 32;

    __shared__ float tile[2][34][68];
    const float* in0 = g_mid + ((size_t)b * QKVC + c0) * NPIX;
    const float* in1 = in0 + NPIX;
    const int tx = threadIdx.x, ty = threadIdx.y;
    const int tid = ty * 8 + tx;

    for (int idx = tid; idx < 34 * 66; idx += 256) {
        int yy = idx / 66, xx = idx - yy * 66;
        int gy = y0 + yy - 1, gx = x0 + xx - 1;
        bool ok = (gy >= 0 && gy < HH && gx >= 0 && gx < WW);
        int off = gy * WW + gx;
        tile[0][yy][xx] = ok ? in0[off] : 0.f;
        tile[1][yy][xx] = ok ? in1[off] : 0.f;
    }
    __syncthreads();

    float sqa[2] = {0.f, 0.f};
#pragma unroll
    for (int cc = 0; cc < 2; cc++) {
        const int c = c0 + cc;
        float w[9];
#pragma unroll
        for (int t = 0; t < 9; t++) w[t] = wdw[c * 9 + t];

#pragma unroll
        for (int half = 0; half < 2; half++) {
            const int bcol = 32 * half + 4 * tx;
            float o0 = 0.f, o1 = 0.f, o2 = 0.f, o3 = 0.f;
#pragma unroll
            for (int ky = 0; ky < 3; ky++) {
                float4 lo = *(float4*)&tile[cc][ty + ky][bcol];
                float4 hi = *(float4*)&tile[cc][ty + ky][bcol + 4];
                float w0 = w[ky * 3], w1 = w[ky * 3 + 1], w2 = w[ky * 3 + 2];
                o0 = fmaf(w0, lo.x, fmaf(w1, lo.y, fmaf(w2, lo.z, o0)));
                o1 = fmaf(w0, lo.y, fmaf(w1, lo.z, fmaf(w2, lo.w, o1)));
                o2 = fmaf(w0, lo.z, fmaf(w1, lo.w, fmaf(w2, hi.x, o2)));
                o3 = fmaf(w0, lo.w, fmaf(w1, hi.x, fmaf(w2, hi.y, o3)));
            }
            *(float4*)&g_qkv[((size_t)b * QKVC + c) * NPIX
                             + (size_t)(y0 + ty) * WW + x0 + bcol] =
                make_float4(o0, o1, o2, o3);
            sqa[cc] = fmaf(o0, o0, fmaf(o1, o1, fmaf(o2, o2, fmaf(o3, o3, sqa[cc]))));
        }
    }

    if (c0 < 2 * DIM) {
        float s0 = sqa[0], s1 = sqa[1];
#pragma unroll
        for (int o = 16; o; o >>= 1) {
            s0 += __shfl_down_sync(0xffffffffu, s0, o);
            s1 += __shfl_down_sync(0xffffffffu, s1, o);
        }
        __shared__ float red[8][2];
        if ((tid & 31) == 0) { red[tid >> 5][0] = s0; red[tid >> 5][1] = s1; }
        __syncthreads();
        if (tid == 0) {
            float t0 = 0.f, t1 = 0.f;
#pragma unroll
            for (int wv = 0; wv < 8; wv++) { t0 += red[wv][0]; t1 += red[wv][1]; }
            atomicAdd(&g_sqn[b * 2 * DIM + c0],     t0);
            atomicAdd(&g_sqn[b * 2 * DIM + c0 + 1], t1);
        }
    }
}

// ---- kernel 3: Gram G = q@k^T, cp.async double-buffered --------------------
// smem: qs[2][32*132] + ks[2][32*132] (dynamic, 67.6 KB -> 3 CTA/SM).
__global__ __launch_bounds__(256) void k_gram() {
    extern __shared__ float sm[];
    float* qs = sm;               // 2 buffers of 32*132
    float* ks = sm + 2 * 4224;

    const int bh = blockIdx.y;
    const int b = bh >> 1, h = bh & 1;
    const long n0 = (long)blockIdx.x * 1024;
    const float* qg = g_qkv + ((size_t)b * QKVC + h * CH) * NPIX + n0;
    const float* kg = g_qkv + ((size_t)b * QKVC + DIM + h * CH) * NPIX + n0;
    const int tid = threadIdx.x;
    const int g  = tid >> 6;
    const int gi = (tid >> 3) & 7;
    const int gj = tid & 7;

    auto issue = [&](int s) {
        float* qb = qs + (s & 1) * 4224;
        float* kb = ks + (s & 1) * 4224;
#pragma unroll
        for (int t = 0; t < 4; t++) {
            int idx = tid + t * 256;          // 0..1023
            int r = idx >> 5, pv = idx & 31;
            cpa16(s2u32(&qb[r * 132 + 4 * pv]), qg + (size_t)r * NPIX + s * 128 + 4 * pv);
            cpa16(s2u32(&kb[r * 132 + 4 * pv]), kg + (size_t)r * NPIX + s * 128 + 4 * pv);
        }
        asm volatile("cp.async.commit_group;");
    };

    u64 acc[4][4];
#pragma unroll
    for (int a = 0; a < 4; a++)
#pragma unroll
        for (int bb = 0; bb < 4; bb++) acc[a][bb] = 0ull;

    issue(0);
    for (int s = 0; s < 8; s++) {
        if (s < 7) issue(s + 1);
        if (s < 7) asm volatile("cp.async.wait_group 1;");
        else       asm volatile("cp.async.wait_group 0;");
        __syncthreads();
        const float* qb = qs + (s & 1) * 4224;
        const float* kb = ks + (s & 1) * 4224;
#pragma unroll 4
        for (int p = g * 32; p < g * 32 + 32; p += 4) {
            ulonglong2 qa[4], kbv[4];
#pragma unroll
            for (int a = 0; a < 4; a++) qa[a] = *(ulonglong2*)&qb[(gi + 8 * a) * 132 + p];
#pragma unroll
            for (int bb = 0; bb < 4; bb++) kbv[bb] = *(ulonglong2*)&kb[(gj + 8 * bb) * 132 + p];
#pragma unroll
            for (int a = 0; a < 4; a++)
#pragma unroll
                for (int bb = 0; bb < 4; bb++) {
                    fma2(acc[a][bb], qa[a].x, kbv[bb].x, acc[a][bb]);
                    fma2(acc[a][bb], qa[a].y, kbv[bb].y, acc[a][bb]);
                }
        }
        __syncthreads();
    }

    float* red = qs;   // reuse first buffer (4224 >= 4096)
#pragma unroll
    for (int a = 0; a < 4; a++)
#pragma unroll
        for (int bb = 0; bb < 4; bb++) {
            float2 r = upk2(acc[a][bb]);
            red[g * 1024 + (gi + 8 * a) * 32 + gj + 8 * bb] = r.x + r.y;
        }
    __syncthreads();
    for (int t = tid; t < 1024; t += 256) {
        float s = red[t] + red[1024 + t] + red[2048 + t] + red[3072 + t];
        atomicAdd(&g_gram[bh * 1024 + t], s);
    }
}

// ---- kernel 4: normalize + triple top-k softmax + combine ------------------
__global__ void k_comb(const float* __restrict__ temp, const float* __restrict__ a1,
                       const float* __restrict__ a2, const float* __restrict__ a3) {
    const int bh = blockIdx.x;
    const int b = bh >> 1, h = bh & 1;
    const int i = threadIdx.x;

    __shared__ float nks[CH];
    float nq = fmaxf(sqrtf(g_sqn[b * 2 * DIM + h * CH + i]), 1e-12f);
    float nk = fmaxf(sqrtf(g_sqn[b * 2 * DIM + DIM + h * CH + i]), 1e-12f);
    nks[i] = nk;
    __syncthreads();

    const float t = temp[h];
    float v[CH];
#pragma unroll
    for (int j = 0; j < CH; j++)
        v[j] = g_gram[bh * CH * CH + i * CH + j] / nq * t / nks[j];

    int rank[CH];
#pragma unroll
    for (int j = 0; j < CH; j++) {
        int r = 0; float vj = v[j];
#pragma unroll
        for (int l = 0; l < CH; l++)
            r += (v[l] > vj) || (v[l] == vj && l < j);
        rank[j] = r;
    }
    float mx = -1e30f;
#pragma unroll
    for (int j = 0; j < CH; j++) mx = fmaxf(mx, v[j]);
    float e[CH], s16 = 0.f, s21 = 0.f, s24 = 0.f;
#pragma unroll
    for (int j = 0; j < CH; j++) {
        float ev = expf(v[j] - mx);
        e[j] = ev;
        if (rank[j] < 16) s16 += ev;
        if (rank[j] < 21) s21 += ev;
        if (rank[j] < 24) s24 += ev;
    }
    const float w1 = a1[0] / s16, w2 = a2[0] / s21, w3 = a3[0] / s24;
#pragma unroll
    for (int j = 0; j < CH; j++) {
        float coef = (rank[j] < 16 ? w1 : 0.f) + (rank[j] < 21 ? w2 : 0.f)
                   + (rank[j] < 24 ? w3 : 0.f);
        g_A[bh * CH * CH + i * CH + j] = e[j] * coef;
    }
}

// ---- kernel 5: M[b] = W_proj @ blockdiag(A) --------------------------------
__global__ void k_buildM(const float* __restrict__ wproj) {
    const int b = blockIdx.x;
    __shared__ float As[HEADS * CH * CH];
    __shared__ float Ws[DIM * DIM];
    const int tid = threadIdx.x;
    for (int idx = tid; idx < HEADS * CH * CH; idx += 128) As[idx] = g_A[b * HEADS * CH * CH + idx];
    for (int idx = tid; idx < DIM * DIM; idx += 128)       Ws[idx] = wproj[idx];
    __syncthreads();
#pragma unroll
    for (int m = 0; m < 32; m++) {
        int idx = tid + 128 * m;
        int o = idx >> 6, ci = idx & 63;
        int h = ci >> 5, cj = ci & 31;
        float s = 0.f;
#pragma unroll
        for (int cp = 0; cp < CH; cp++)
            s = fmaf(Ws[o * DIM + h * CH + cp], As[h * CH * CH + cp * CH + cj], s);
        g_M[b * DIM * DIM + idx] = s;
    }
}

// ---- kernel 6: out = M[b] @ v (R15 winner, flat 256-thread block) ----------
__global__ __launch_bounds__(256) void k_out(float* __restrict__ out) {
    extern __shared__ float sm[];
    u64*   ms2 = (u64*)sm;            // [64ci][64oc] u64 {m,m}
    float* vs  = sm + 64 * 64 * 2;    // [64][256]
    const int b = blockIdx.y;
    const long n0 = (long)blockIdx.x * 256;
    const int tid = threadIdx.x;
    const int og = tid >> 5;
    const int pg = tid & 31;

    const float* Mb = g_M + b * DIM * DIM;
    for (int idx = tid; idx < DIM * DIM; idx += 256) {
        int o = idx >> 6, ci = idx & 63;
        float m = Mb[idx];
        ms2[ci * DIM + o] = pk2(m, m);
    }
    const float* vg = g_qkv + ((size_t)b * QKVC + 2 * DIM) * NPIX + n0;
    for (int idx = tid; idx < 64 * 64; idx += 256) {
        int ci = idx >> 6, pv = idx & 63;
        ((float4*)&vs[ci * 256])[pv] = ((const float4*)(vg + (size_t)ci * NPIX))[pv];
    }
    __syncthreads();

    u64 acc[8][4];
#pragma unroll
    for (int i = 0; i < 8; i++)
#pragma unroll
        for (int j = 0; j < 4; j++) acc[i][j] = 0ull;

    const int ob8 = og * 8;
#pragma unroll 4
    for (int ci = 0; ci < 64; ci++) {
        const ulonglong2* wp = (const ulonglong2*)(ms2 + ci * DIM + ob8);
        ulonglong2 wA = wp[0], wB = wp[1], wC = wp[2], wD = wp[3];
        u64 wd[8] = {wA.x, wA.y, wB.x, wB.y, wC.x, wC.y, wD.x, wD.y};
        u64 xp[4];
#pragma unroll
        for (int j = 0; j < 4; j++)
            xp[j] = *(const u64*)&vs[ci * 256 + 2 * (pg + 32 * j)];
#pragma unroll
        for (int i = 0; i < 8; i++)
#pragma unroll
            for (int j = 0; j < 4; j++)
                fma2(acc[i][j], wd[i], xp[j], acc[i][j]);
    }

    float* ob = out + (size_t)b * DIM * NPIX + n0;
#pragma unroll
    for (int i = 0; i < 8; i++)
#pragma unroll
        for (int j = 0; j < 4; j++) {
            float2 r = upk2(acc[i][j]);
            *(float2*)&ob[(size_t)(ob8 + i) * NPIX + 2 * (pg + 32 * j)] = r;
        }
}

extern "C" void kernel_launch(void* const* d_in, const int* in_sizes, int n_in,
                              void* d_out, int out_size) {
    const float* x     = (const float*)d_in[0];
    const float* wqkv  = (const float*)d_in[1];
    const float* wdw   = (const float*)d_in[2];
    const float* wproj = (const float*)d_in[3];
    const float* temp  = (const float*)d_in[4];
    const float* a1    = (const float*)d_in[5];
    const float* a2    = (const float*)d_in[6];
    const float* a3    = (const float*)d_in[7];
    float* out = (float*)d_out;

    cudaFuncSetAttribute(k_gram, cudaFuncAttributeMaxDynamicSharedMemorySize, 69632);
    cudaFuncSetAttribute(k_out,  cudaFuncAttributeMaxDynamicSharedMemorySize, 98304);

    k_zero<<<64, 256>>>();
    k_conv1<<<dim3(1024, 8, 2), dim3(16, 16)>>>(x, wqkv);
    k_dw<<<dim3(4, 8, B * 96), dim3(8, 32)>>>(wdw);
    k_gram<<<dim3(64, 16), 256, 67584>>>();
    k_comb<<<16, 32>>>(temp, a1, a2, a3);
    k_buildM<<<8, 128>>>(wproj);
    k_out<<<dim3(256, 8), dim3(256, 1), 98304>>>(out);
}